// round 17
// baseline (speedup 1.0000x reference)
#include <cuda_runtime.h>
#include <cuda_fp16.h>
#include <math.h>
#include <stdint.h>

#define B_   8
#define CIN  64
#define COUT 32
#define HIN  128
#define WIN  128
#define HO   256
#define WO   256
#define ATT  16
#define KNUM 2
#define EPS  1e-5f
#define RATIO 0.49803921568627452f   // 127/255

typedef unsigned long long u64;
typedef unsigned int u32;

// Scratch device globals
__device__ float g_gap[B_ * CIN];                 // mean of upsampled x
// upsampled image, fp16, layout [b][g=ci/8][oy][ox][8ci] (uint4 per px-chunk)
__device__ __half g_xh[(size_t)B_ * CIN * HO * WO];
// folded per-sample weights, fp16, layout [b][q][co][ci]
__device__ __half g_w[B_ * 9 * COUT * CIN];
__device__ float g_bias[COUT];

// ---------------- warp-level MMA helpers (plain sm_103 PTX, sm_80+) --------
__device__ __forceinline__ u32 smem_to_u32(const void* p) {
    u32 a;
    asm("{ .reg .u64 t; cvta.to.shared.u64 t, %1; cvt.u32.u64 %0, t; }"
        : "=r"(a) : "l"(p));
    return a;
}
__device__ __forceinline__ void ldsm_x4(u32* r, u32 addr) {
    asm volatile("ldmatrix.sync.aligned.m8n8.x4.shared.b16 {%0,%1,%2,%3}, [%4];"
                 : "=r"(r[0]), "=r"(r[1]), "=r"(r[2]), "=r"(r[3]) : "r"(addr));
}
__device__ __forceinline__ void ldsm_x2(u32* r, u32 addr) {
    asm volatile("ldmatrix.sync.aligned.m8n8.x2.shared.b16 {%0,%1}, [%2];"
                 : "=r"(r[0]), "=r"(r[1]) : "r"(addr));
}
__device__ __forceinline__ void mma_fp16(float* c, const u32* a, const u32* b) {
    asm volatile(
        "mma.sync.aligned.m16n8k16.row.col.f32.f16.f16.f32 "
        "{%0,%1,%2,%3}, {%4,%5,%6,%7}, {%8,%9}, {%0,%1,%2,%3};"
        : "+f"(c[0]), "+f"(c[1]), "+f"(c[2]), "+f"(c[3])
        : "r"(a[0]), "r"(a[1]), "r"(a[2]), "r"(a[3]), "r"(b[0]), "r"(b[1]));
}
__device__ __forceinline__ void cp16(u32 saddr, const void* gaddr, u32 srcsz) {
    asm volatile("cp.async.cg.shared.global [%0], [%1], 16, %2;"
                 :: "r"(saddr), "l"(gaddr), "r"(srcsz));
}

// ---------------------------------------------------------------------------
// K_gap: GAP of the virtual upsample via separable row weights R
// ---------------------------------------------------------------------------
__global__ void k_gap(const float* __restrict__ x)
{
    __shared__ float sR[HIN];
    __shared__ float red[256];
    int t = threadIdx.x;
    if (t < HIN) sR[t] = 0.0f;
    __syncthreads();
    if (t < HO) {
        float py = (float)t * RATIO;
        int   y0 = (int)py;
        float wy = py - (float)y0;
        int   y1 = min(y0 + 1, HIN - 1);
        atomicAdd(&sR[y0], 1.0f - wy);
        atomicAdd(&sR[y1], wy);
    }
    __syncthreads();
    int bc = blockIdx.x;
    const float* __restrict__ plane = x + (size_t)bc * HIN * WIN;
    float lsum = 0.0f;
    for (int idx = t; idx < HIN * WIN; idx += 256) {
        int y = idx >> 7, c = idx & 127;
        lsum += plane[idx] * sR[y] * sR[c];
    }
    red[t] = lsum;
    __syncthreads();
    for (int s = 128; s > 0; s >>= 1) {
        if (t < s) red[t] += red[t + s];
        __syncthreads();
    }
    if (t == 0) g_gap[bc] = red[0] * (1.0f / (float)(HO * WO));
}

// ---------------------------------------------------------------------------
// K1: bilinear x2 upsample -> fp16 planes (two-phase: row-interp then col)
// ---------------------------------------------------------------------------
__global__ void __launch_bounds__(256) k_upsample(const float* __restrict__ x)
{
    __shared__ float sX[8][2][WIN];
    __shared__ float sRI[8][WIN];

    int oy = blockIdx.x;
    int g  = blockIdx.y;
    int b  = blockIdx.z;
    int ox = threadIdx.x;

    float py = (float)oy * RATIO;
    int   y0 = (int)py;
    float wy = py - (float)y0;
    int   y1 = min(y0 + 1, HIN - 1);

    const float* base = x + ((size_t)b * CIN + g * 8) * (HIN * WIN);
    for (int i = threadIdx.x; i < 8 * 2 * WIN; i += 256) {
        int k = i >> 8;
        int r = (i >> 7) & 1;
        int c = i & 127;
        sX[k][r][c] = __ldg(base + (size_t)k * (HIN * WIN) +
                            (r ? y1 : y0) * WIN + c);
    }
    __syncthreads();

    for (int i = threadIdx.x; i < 8 * WIN; i += 256) {
        int k = i >> 7, c = i & 127;
        sRI[k][c] = sX[k][0][c] * (1.0f - wy) + sX[k][1][c] * wy;
    }
    __syncthreads();

    float px = (float)ox * RATIO;
    int   x0 = (int)px;
    float wx = px - (float)x0;
    int   x1 = min(x0 + 1, WIN - 1);

    u32 hw[4];
    #pragma unroll
    for (int j = 0; j < 4; j++) {
        int k0 = 2 * j, k1 = 2 * j + 1;
        float va = sRI[k0][x0] * (1.0f - wx) + sRI[k0][x1] * wx;
        float vb = sRI[k1][x0] * (1.0f - wx) + sRI[k1][x1] * wx;
        u32 p = (u32)__half_as_ushort(__float2half(va));
        p |= (u32)__half_as_ushort(__float2half(vb)) << 16;
        hw[j] = p;
    }
    ((uint4*)g_xh)[((size_t)(b * 8 + g) * HO + oy) * WO + ox] =
        make_uint4(hw[0], hw[1], hw[2], hw[3]);
}

// ---------------------------------------------------------------------------
// K2: attention MLP + weight fold -> fp16 weights [b][q][co][ci]
// ---------------------------------------------------------------------------
__global__ void k_attention(
    const float* __restrict__ fc_w,
    const float* __restrict__ bna_g, const float* __restrict__ bna_b,
    const float* __restrict__ bna_m, const float* __restrict__ bna_v,
    const float* __restrict__ ch_w,  const float* __restrict__ ch_b,
    const float* __restrict__ fil_w, const float* __restrict__ fil_b,
    const float* __restrict__ sp_w,  const float* __restrict__ sp_b,
    const float* __restrict__ k_w,   const float* __restrict__ k_b,
    const float* __restrict__ weight,
    const float* __restrict__ bn_g,  const float* __restrict__ bn_b,
    const float* __restrict__ bn_m,  const float* __restrict__ bn_v)
{
    int b = blockIdx.x;
    int t = threadIdx.x;
    __shared__ float sh[ATT];
    __shared__ float sch[CIN];
    __shared__ float sfs[COUT];
    __shared__ float ssp[9];
    __shared__ float sraw[KNUM];
    __shared__ float skk[KNUM];

    if (t < ATT) {
        const float* g = g_gap + b * CIN;
        float acc = 0.0f;
        #pragma unroll
        for (int ci = 0; ci < CIN; ci++) acc += fc_w[t * CIN + ci] * g[ci];
        acc = (acc - bna_m[t]) * rsqrtf(bna_v[t] + EPS) * bna_g[t] + bna_b[t];
        sh[t] = fmaxf(acc, 0.0f);
    }
    __syncthreads();
    if (t < CIN) {
        float a = ch_b[t];
        #pragma unroll
        for (int j = 0; j < ATT; j++) a += ch_w[t * ATT + j] * sh[j];
        sch[t] = 1.0f / (1.0f + expf(-a));
    } else if (t < CIN + COUT) {
        int co = t - CIN;
        float a = fil_b[co];
        #pragma unroll
        for (int j = 0; j < ATT; j++) a += fil_w[co * ATT + j] * sh[j];
        float fil = 1.0f / (1.0f + expf(-a));
        sfs[co] = fil * bn_g[co] * rsqrtf(bn_v[co] + EPS);
    } else if (t < CIN + COUT + 9) {
        int q = t - CIN - COUT;
        float a = sp_b[q];
        #pragma unroll
        for (int j = 0; j < ATT; j++) a += sp_w[q * ATT + j] * sh[j];
        ssp[q] = 1.0f / (1.0f + expf(-a));
    } else if (t < CIN + COUT + 9 + KNUM) {
        int k = t - CIN - COUT - 9;
        float a = k_b[k];
        #pragma unroll
        for (int j = 0; j < ATT; j++) a += k_w[k * ATT + j] * sh[j];
        sraw[k] = a;
    }
    __syncthreads();
    if (t == 0) {
        float m  = fmaxf(sraw[0], sraw[1]);
        float e0 = expf(sraw[0] - m);
        float e1 = expf(sraw[1] - m);
        float inv = 1.0f / (e0 + e1);
        skk[0] = e0 * inv;
        skk[1] = e1 * inv;
    }
    __syncthreads();

    const int WSZ = COUT * CIN * 9;
    for (int idx = t; idx < WSZ; idx += blockDim.x) {
        int co  = idx / (CIN * 9);
        int rem = idx % (CIN * 9);
        int ci  = rem / 9;
        int q   = rem % 9;
        float w = skk[0] * weight[idx] + skk[1] * weight[WSZ + idx];
        w = w * ssp[q] * sch[ci] * sfs[co];
        g_w[(((size_t)b * 9 + q) * COUT + co) * CIN + ci] = __float2half(w);
    }
    if (b == 0 && t < COUT)
        g_bias[t] = bn_b[t] - bn_m[t] * bn_g[t] * rsqrtf(bn_v[t] + EPS);
}

// ---------------------------------------------------------------------------
// K3: persistent implicit-GEMM conv, 32px x 32cout warp tiles (2 wf/MMA).
// 296 CTAs (2/SM), each pinned to one b. CTA tile = 4 rows x 64 cols.
// A: SINGLE smem buffer (6 rows x 66 px, 50.7 KB); next tile prefetched
// into registers (13x LDG.128/thread) during the mainloop, stored after the
// post-mainloop barrier. B (36.9 KB) loaded once. smem 87.6 KB.
// ---------------------------------------------------------------------------
#define AROWB 8448            // 66 * 128 bytes
#define OFF_B 0               // 9 * 4096 = 36864
#define OFF_A 36864
#define SMEM_TOTAL (OFF_A + 6 * AROWB)   // 87552
#define NSLOT 37              // 296 / 8 CTAs per sample
#define NTILE 256             // tiles per sample: 64 row-tiles x 4 col-tiles
#define AITEMS 3168           // 6 * 8 * 66 uint4 per A tile
#define PFN 13                // ceil(3168 / 256)

#define SWZC(byte, r) ((byte) ^ (((r) & 7) << 4))

__device__ __forceinline__ void prefetch_A_async(u32 sbA, int b, int ty,
                                                 int tx, int tid)
{
    const uint4* xh4 = (const uint4*)g_xh;
    for (int i = tid; i < AITEMS; i += 256) {
        int row = i / 528;
        int rem = i % 528;
        int g   = rem / 66;
        int p   = rem % 66;
        int oy  = ty * 4 - 1 + row;
        int oc  = tx * 64 - 1 + p;
        bool ok = ((unsigned)oy < (unsigned)HO) && ((unsigned)oc < (unsigned)WO);
        const uint4* gp = xh4 +
            ((size_t)(b * 8 + g) * HO + (ok ? oy : 0)) * WO + (ok ? oc : 0);
        cp16(sbA + row * AROWB + p * 128 + SWZC(g * 16, p), gp, ok ? 16u : 0u);
    }
}

__global__ void __launch_bounds__(256, 2)
k_conv(float* __restrict__ out)
{
    extern __shared__ char smem[];
    u32 sb = smem_to_u32(smem);
    int tid  = threadIdx.x;
    int w    = tid >> 5;
    int lane = tid & 31;
    int b    = blockIdx.x & 7;
    int slot = blockIdx.x >> 3;          // 0..36

    int wrow = w >> 1;            // output row within 4-row tile (0..3)
    int wcol = (w & 1) * 32;      // col base within 64-tile

    const uint4* xh4 = (const uint4*)g_xh;

    // ---- prologue: B (once) + A(tile0) via cp.async -----------------------
    for (int i = tid; i < 2304; i += 256) {
        int q    = i / 256;
        int rem2 = i % 256;
        int n    = rem2 >> 3;
        int g    = rem2 & 7;
        const void* gp = (const void*)(g_w +
            (((size_t)b * 9 + q) * COUT + n) * CIN + g * 8);
        cp16(sb + OFF_B + q * 4096 + n * 128 + SWZC(g * 16, n), gp, 16u);
    }
    if (slot < NTILE)
        prefetch_A_async(sb + OFF_A, b, slot >> 2, slot & 3, tid);
    asm volatile("cp.async.commit_group;" ::: "memory");
    asm volatile("cp.async.wait_group 0;" ::: "memory");
    __syncthreads();

    for (int lt = slot; lt < NTILE; lt += NSLOT) {
        int ty = lt >> 2, tx = lt & 3;
        int nlt = lt + NSLOT;
        bool havenext = (nlt < NTILE);

        // ---- prefetch next A tile into registers (overlaps mainloop) ------
        uint4 pre[PFN];
        if (havenext) {
            int nty = nlt >> 2, ntx = nlt & 3;
            #pragma unroll
            for (int j = 0; j < PFN; j++) {
                int i = tid + j * 256;
                int row = i / 528;
                int rem = i % 528;
                int g   = rem / 66;
                int p   = rem % 66;
                int oy  = nty * 4 - 1 + row;
                int oc  = ntx * 64 - 1 + p;
                int cy  = min(max(oy, 0), HO - 1);
                int cc  = min(max(oc, 0), WO - 1);
                const uint4* gp = xh4 +
                    ((size_t)(b * 8 + min(g, 7)) * HO + cy) * WO + cc;
                pre[j] = (i < AITEMS) ? __ldg(gp) : make_uint4(0, 0, 0, 0);
            }
        }

        // ---- mainloop: 9 taps x 4 k-steps, warp = 32px x 32cout -----------
        float acc[2][4][4];
        #pragma unroll
        for (int mt = 0; mt < 2; mt++)
            #pragma unroll
            for (int nt = 0; nt < 4; nt++)
                #pragma unroll
                for (int r = 0; r < 4; r++) acc[mt][nt][r] = 0.0f;

        #pragma unroll 1
        for (int q = 0; q < 9; q++) {
            int ky = q / 3, kx = q % 3;
            u32 arow  = sb + OFF_A + (wrow + ky) * AROWB;
            u32 bbase = sb + OFF_B + q * 4096;
            #pragma unroll
            for (int ks = 0; ks < 4; ks++) {
                int kb = ks * 32;
                u32 bfr[4][2];
                #pragma unroll
                for (int nt = 0; nt < 4; nt++) {
                    int n = nt * 8 + (lane & 7);
                    ldsm_x2(bfr[nt], bbase + n * 128 +
                            SWZC(kb + ((lane >> 3) & 1) * 16, n));
                }
                u32 afr[2][4];
                #pragma unroll
                for (int mt = 0; mt < 2; mt++) {
                    int p = wcol + mt * 16 + (lane & 15) + kx;
                    ldsm_x4(afr[mt], arow + p * 128 +
                            SWZC(kb + ((lane >> 4) ? 16 : 0), p));
                }
                #pragma unroll
                for (int mt = 0; mt < 2; mt++)
                    #pragma unroll
                    for (int nt = 0; nt < 4; nt++)
                        mma_fp16(acc[mt][nt], afr[mt], bfr[nt]);
            }
        }

        // ---- epilogue (register-only): bias + exact GELU ------------------
        int row = ty * 4 + wrow;
        #pragma unroll
        for (int mt = 0; mt < 2; mt++) {
            int colb = tx * 64 + wcol + mt * 16 + (lane >> 2);
            #pragma unroll
            for (int nt = 0; nt < 4; nt++) {
                int co0 = nt * 8 + (lane & 3) * 2;
                float b0 = g_bias[co0];
                float b1 = g_bias[co0 + 1];
                #pragma unroll
                for (int r = 0; r < 4; r++) {
                    int co = co0 + (r & 1);
                    int cc = colb + ((r >> 1) ? 8 : 0);
                    float v = acc[mt][nt][r] + ((r & 1) ? b1 : b0);
                    out[(((size_t)b * COUT + co) * HO + row) * WO + cc] =
                        0.5f * v * (1.0f + erff(v * 0.70710678118654752f));
                }
            }
        }

        // ---- store prefetched A tile into the (now free) buffer -----------
        __syncthreads();
        if (havenext) {
            int nty = nlt >> 2, ntx = nlt & 3;
            #pragma unroll
            for (int j = 0; j < PFN; j++) {
                int i = tid + j * 256;
                if (i < AITEMS) {
                    int row = i / 528;
                    int rem = i % 528;
                    int g   = rem / 66;
                    int p   = rem % 66;
                    int oy  = nty * 4 - 1 + row;
                    int oc  = ntx * 64 - 1 + p;
                    uint4 v = pre[j];
                    if ((unsigned)oy >= (unsigned)HO ||
                        (unsigned)oc >= (unsigned)WO)
                        v = make_uint4(0, 0, 0, 0);
                    *(uint4*)(smem + OFF_A + row * AROWB + p * 128 +
                              SWZC(g * 16, p)) = v;
                }
            }
            __syncthreads();
        }
    }
}

// ---------------------------------------------------------------------------
extern "C" void kernel_launch(void* const* d_in, const int* in_sizes, int n_in,
                              void* d_out, int out_size)
{
    const float* x      = (const float*)d_in[0];
    const float* fc_w   = (const float*)d_in[1];
    const float* bna_g  = (const float*)d_in[2];
    const float* bna_b  = (const float*)d_in[3];
    const float* bna_m  = (const float*)d_in[4];
    const float* bna_v  = (const float*)d_in[5];
    const float* ch_w   = (const float*)d_in[6];
    const float* ch_b   = (const float*)d_in[7];
    const float* fil_w  = (const float*)d_in[8];
    const float* fil_b  = (const float*)d_in[9];
    const float* sp_w   = (const float*)d_in[10];
    const float* sp_b   = (const float*)d_in[11];
    const float* k_w    = (const float*)d_in[12];
    const float* k_b    = (const float*)d_in[13];
    const float* weight = (const float*)d_in[14];
    const float* bn_g   = (const float*)d_in[15];
    const float* bn_b   = (const float*)d_in[16];
    const float* bn_m   = (const float*)d_in[17];
    const float* bn_v   = (const float*)d_in[18];

    cudaFuncSetAttribute(k_conv, cudaFuncAttributeMaxDynamicSharedMemorySize,
                         SMEM_TOTAL);

    k_gap<<<B_ * CIN, 256>>>(x);
    k_upsample<<<dim3(HO, 8, B_), 256>>>(x);
    k_attention<<<B_, 256>>>(fc_w, bna_g, bna_b, bna_m, bna_v,
                             ch_w, ch_b, fil_w, fil_b, sp_w, sp_b, k_w, k_b,
                             weight, bn_g, bn_b, bn_m, bn_v);
    k_conv<<<NSLOT * B_, 256, SMEM_TOTAL>>>((float*)d_out);
}